// round 4
// baseline (speedup 1.0000x reference)
#include <cuda_runtime.h>

#define NMAX 50000
#define EMAX 1600000
#define HC   64
#define NEG_SLOPE 0.2f

// ---------------- device scratch (no allocation allowed) ----------------
__device__ float g_xl [NMAX * HC];     // source-side transform
__device__ float g_xr [NMAX * HC];     // target-side transform
__device__ float g_h  [NMAX * HC];     // activated layer output
__device__ int   g_deg[NMAX];          // in-degree histogram
__device__ int   g_off[NMAX + 1];      // CSR offsets
__device__ int   g_pos[NMAX];          // scatter cursors
__device__ int   g_csr_src[EMAX];      // src node per CSR slot (sorted by dst)
__device__ int   g_is64;               // 1 if edge_index is int64, 0 if int32

__device__ __forceinline__ float lrelu(float v) {
    return v > 0.f ? v : NEG_SLOPE * v;
}

// ---------------- edge_index dtype detection ------------------------------
__global__ void detect_dtype_kernel(const int* __restrict__ w) {
    if (threadIdx.x == 0 && blockIdx.x == 0) {
        int any = 0;
        for (int i = 0; i < 64; i++) any |= w[2 * i + 1];
        g_is64 = (any == 0) ? 1 : 0;
    }
}

__device__ __forceinline__ int load_idx(const void* ei, int i) {
    return g_is64 ? (int)((const long long*)ei)[i] : ((const int*)ei)[i];
}

// ---------------- CSR build ----------------------------------------------
__global__ void hist_kernel(const void* __restrict__ ei, int E) {
    int e = blockIdx.x * blockDim.x + threadIdx.x;
    if (e >= E) return;
    atomicAdd(&g_deg[load_idx(ei, e + E)], 1);
}

__global__ void __launch_bounds__(1024) scan_kernel(int N) {
    __shared__ int part[1024];
    int t = threadIdx.x;
    int chunk = (N + 1023) >> 10;
    int b = t * chunk; if (b > N) b = N;
    int e = b + chunk; if (e > N) e = N;
    int s = 0;
    for (int i = b; i < e; i++) s += g_deg[i];
    part[t] = s;
    __syncthreads();
    for (int d = 1; d < 1024; d <<= 1) {
        int v = (t >= d) ? part[t - d] : 0;
        __syncthreads();
        part[t] += v;
        __syncthreads();
    }
    int run = (t == 0) ? 0 : part[t - 1];
    for (int i = b; i < e; i++) {
        g_off[i] = run;
        g_pos[i] = run;
        run += g_deg[i];
    }
    if (e == N) g_off[N] = run;
}

__global__ void scatter_kernel(const void* __restrict__ ei, int E) {
    int e = blockIdx.x * blockDim.x + threadIdx.x;
    if (e >= E) return;
    int s = load_idx(ei, e);
    int d = load_idx(ei, e + E);
    int slot = atomicAdd(&g_pos[d], 1);
    g_csr_src[slot] = s;
}

// ---------------- packed f32x2 helpers ------------------------------------
__device__ __forceinline__ unsigned long long pack_dup(float v) {
    unsigned long long r;
    asm("mov.b64 %0, {%1, %1};" : "=l"(r) : "f"(v));
    return r;
}
__device__ __forceinline__ void fma2(unsigned long long& acc,
                                     unsigned long long a,
                                     unsigned long long b) {
    asm("fma.rn.f32x2 %0, %1, %2, %0;" : "+l"(acc) : "l"(a), "l"(b));
}
__device__ __forceinline__ float2 unpack2(unsigned long long v) {
    float2 f;
    asm("mov.b64 {%0, %1}, %2;" : "=f"(f.x), "=f"(f.y) : "l"(v));
    return f;
}

// ---------------- dual GEMM with packed f32x2 math -------------------------
// C[z][M,NC] = A[M,K] @ W[z][K,NC] + bias[z]; blockIdx.z selects z.
// BM=256, BN=64, BK=32, 256 threads, per-thread 8Mx8N as 4 M-pairs x 8 N.
template<int ACT>  // 0 = none, 1 = sigmoid
__global__ void __launch_bounds__(256) gemm2_kernel(
    const float* __restrict__ A,
    const float* __restrict__ W0, const float* __restrict__ b0, float* __restrict__ C0,
    const float* __restrict__ W1, const float* __restrict__ b1, float* __restrict__ C1,
    int M, int K, int NC)
{
    const float* W    = blockIdx.z ? W1 : W0;
    const float* bias = blockIdx.z ? b1 : b0;
    float*       C    = blockIdx.z ? C1 : C0;

    __shared__ __align__(16) float As[32 * 264];   // [k][m], stride 264
    __shared__ __align__(16) float Ws[32 * 64];    // [k][n]

    const int tid = threadIdx.x;
    const int bm  = blockIdx.x * 256;
    const int bn  = blockIdx.y * 64;
    const int tx  = tid & 7;          // n group
    const int ty  = tid >> 3;         // m group (0..31)
    const int m0  = ty * 8;
    const int n0  = tx * 8;

    unsigned long long acc[4][8];
#pragma unroll
    for (int i = 0; i < 4; i++)
#pragma unroll
        for (int j = 0; j < 8; j++) acc[i][j] = 0ull;

    for (int kk = 0; kk < K; kk += 32) {
        // load A tile (256 rows x 32 k) transposed into As[k][m]
#pragma unroll
        for (int i = 0; i < 8; i++) {
            int f   = tid + i * 256;
            int row = f >> 3;       // 0..255
            int c4  = f & 7;        // k quad
            float4 v = make_float4(0.f, 0.f, 0.f, 0.f);
            if (bm + row < M)
                v = *(const float4*)(A + (size_t)(bm + row) * K + kk + c4 * 4);
            As[(c4 * 4 + 0) * 264 + row] = v.x;
            As[(c4 * 4 + 1) * 264 + row] = v.y;
            As[(c4 * 4 + 2) * 264 + row] = v.z;
            As[(c4 * 4 + 3) * 264 + row] = v.w;
        }
        // load W tile (32 k x 64 n)
#pragma unroll
        for (int i = 0; i < 2; i++) {
            int f  = tid + i * 256;
            int kr = f >> 4;
            int cw = (f & 15) * 4;
            *(float4*)&Ws[kr * 64 + cw] =
                *(const float4*)(W + (size_t)(kk + kr) * NC + bn + cw);
        }
        __syncthreads();

#pragma unroll 8
        for (int k = 0; k < 32; k++) {
            // a-pairs: 8 consecutive M values = 4 f32x2
            const unsigned long long* ap =
                (const unsigned long long*)(As + k * 264 + m0);
            unsigned long long a2[4];
            a2[0] = ap[0]; a2[1] = ap[1]; a2[2] = ap[2]; a2[3] = ap[3];
            // w values: 8 scalars, duplicated into pairs
            float4 wA = *(const float4*)(Ws + k * 64 + n0);
            float4 wB = *(const float4*)(Ws + k * 64 + n0 + 4);
            unsigned long long w2[8];
            w2[0] = pack_dup(wA.x); w2[1] = pack_dup(wA.y);
            w2[2] = pack_dup(wA.z); w2[3] = pack_dup(wA.w);
            w2[4] = pack_dup(wB.x); w2[5] = pack_dup(wB.y);
            w2[6] = pack_dup(wB.z); w2[7] = pack_dup(wB.w);
#pragma unroll
            for (int i = 0; i < 4; i++)
#pragma unroll
                for (int j = 0; j < 8; j++)
                    fma2(acc[i][j], a2[i], w2[j]);
        }
        __syncthreads();
    }

    // epilogue
    float bv[8];
#pragma unroll
    for (int j = 0; j < 8; j++) bv[j] = bias[bn + n0 + j];

#pragma unroll
    for (int i = 0; i < 4; i++) {
        int r0 = bm + m0 + 2 * i;
        float o0[8], o1[8];
#pragma unroll
        for (int j = 0; j < 8; j++) {
            float2 p = unpack2(acc[i][j]);
            float v0 = p.x + bv[j];
            float v1 = p.y + bv[j];
            if (ACT == 1) {
                v0 = 1.f / (1.f + __expf(-v0));
                v1 = 1.f / (1.f + __expf(-v1));
            }
            o0[j] = v0; o1[j] = v1;
        }
        if (r0 < M) {
            *(float4*)(C + (size_t)r0 * NC + bn + n0)     = make_float4(o0[0], o0[1], o0[2], o0[3]);
            *(float4*)(C + (size_t)r0 * NC + bn + n0 + 4) = make_float4(o0[4], o0[5], o0[6], o0[7]);
        }
        if (r0 + 1 < M) {
            *(float4*)(C + (size_t)(r0 + 1) * NC + bn + n0)     = make_float4(o1[0], o1[1], o1[2], o1[3]);
            *(float4*)(C + (size_t)(r0 + 1) * NC + bn + n0 + 4) = make_float4(o1[4], o1[5], o1[6], o1[7]);
        }
    }
}

// ---------------- fused per-node GATv2 aggregation ------------------------
__device__ __forceinline__ void gat_edge_step(
    float2 xv, float2 xrv, float a0, float a1,
    float& accx, float& accy, float& den)
{
    float p = a0 * lrelu(xv.x + xrv.x) + a1 * lrelu(xv.y + xrv.y);
    p += __shfl_xor_sync(0xffffffffu, p, 1);
    p += __shfl_xor_sync(0xffffffffu, p, 2);
    p += __shfl_xor_sync(0xffffffffu, p, 4);
    float ex = __expf(p);
    den  += ex;
    accx += ex * xv.x;
    accy += ex * xv.y;
}

__global__ void __launch_bounds__(256) gat_aggregate_kernel(
    const float* __restrict__ xl, const float* __restrict__ xr,
    const float* __restrict__ att, const float* __restrict__ bias,
    float* __restrict__ out, int N)
{
    int warp = (blockIdx.x * blockDim.x + threadIdx.x) >> 5;
    int c    = threadIdx.x & 31;
    if (warp >= N) return;
    const int d = warp;

    const float a0 = att[2 * c];
    const float a1 = att[2 * c + 1];
    const float2 xrv = *(const float2*)(xr + (size_t)d * 64 + 2 * c);

    const int beg = g_off[d];
    const int end = g_off[d + 1];

    float accx = 0.f, accy = 0.f, den = 0.f;

    for (int i = beg; i < end; ) {
        int cnt = end - i;
        if (cnt > 32) cnt = 32;
        int my_src = (c < cnt) ? g_csr_src[i + c] : 0;

        int j = 0;
        for (; j + 4 <= cnt; j += 4) {
            int s0 = __shfl_sync(0xffffffffu, my_src, j);
            int s1 = __shfl_sync(0xffffffffu, my_src, j + 1);
            int s2 = __shfl_sync(0xffffffffu, my_src, j + 2);
            int s3 = __shfl_sync(0xffffffffu, my_src, j + 3);
            float2 v0 = *(const float2*)(xl + (size_t)s0 * 64 + 2 * c);
            float2 v1 = *(const float2*)(xl + (size_t)s1 * 64 + 2 * c);
            float2 v2 = *(const float2*)(xl + (size_t)s2 * 64 + 2 * c);
            float2 v3 = *(const float2*)(xl + (size_t)s3 * 64 + 2 * c);
            gat_edge_step(v0, xrv, a0, a1, accx, accy, den);
            gat_edge_step(v1, xrv, a0, a1, accx, accy, den);
            gat_edge_step(v2, xrv, a0, a1, accx, accy, den);
            gat_edge_step(v3, xrv, a0, a1, accx, accy, den);
        }
        for (; j < cnt; j++) {
            int s = __shfl_sync(0xffffffffu, my_src, j);
            float2 v = *(const float2*)(xl + (size_t)s * 64 + 2 * c);
            gat_edge_step(v, xrv, a0, a1, accx, accy, den);
        }
        i += cnt;
    }

    float inv = (den > 0.f) ? (1.f / den) : 0.f;
    float ox = fmaxf(accx * inv + bias[2 * c],     0.f);
    float oy = fmaxf(accy * inv + bias[2 * c + 1], 0.f);
    *(float2*)(out + (size_t)d * 64 + 2 * c) = make_float2(ox, oy);
}

// ---------------- launch --------------------------------------------------
extern "C" void kernel_launch(void* const* d_in, const int* in_sizes, int n_in,
                              void* d_out, int out_size)
{
    const float* x    = (const float*)d_in[0];
    const void*  ei   = d_in[1];
    const float* Wl1  = (const float*)d_in[2];
    const float* bl1  = (const float*)d_in[3];
    const float* Wr1  = (const float*)d_in[4];
    const float* br1  = (const float*)d_in[5];
    const float* att1 = (const float*)d_in[6];
    const float* bias1= (const float*)d_in[7];
    const float* Wl2  = (const float*)d_in[8];
    const float* bl2  = (const float*)d_in[9];
    const float* Wr2  = (const float*)d_in[10];
    const float* br2  = (const float*)d_in[11];
    const float* att2 = (const float*)d_in[12];
    const float* bias2= (const float*)d_in[13];
    const float* Wo   = (const float*)d_in[14];
    const float* bo   = (const float*)d_in[15];

    const int Nn = in_sizes[0] / 256;      // 50000
    const int E  = in_sizes[1] / 2;        // 1600000

    float *p_xl, *p_xr, *p_h;
    int *p_deg;
    cudaGetSymbolAddress((void**)&p_xl,  g_xl);
    cudaGetSymbolAddress((void**)&p_xr,  g_xr);
    cudaGetSymbolAddress((void**)&p_h,   g_h);
    cudaGetSymbolAddress((void**)&p_deg, g_deg);

    const int gm = (Nn + 255) / 256;       // 196
    const dim3 blk(256);
    const int ebl = (E + 255) / 256;
    const int agb = (Nn * 32 + 255) / 256;

    // ---- CSR build (shared by both layers) ----
    detect_dtype_kernel<<<1, 32>>>((const int*)ei);
    cudaMemsetAsync(p_deg, 0, (size_t)Nn * sizeof(int));
    hist_kernel<<<ebl, blk>>>(ei, E);
    scan_kernel<<<1, 1024>>>(Nn);
    scatter_kernel<<<ebl, blk>>>(ei, E);

    // ---- layer 1: xl, xr in one dual-GEMM launch ----
    gemm2_kernel<0><<<dim3(gm, 1, 2), blk>>>(x, Wl1, bl1, p_xl, Wr1, br1, p_xr,
                                             Nn, 256, 64);
    gat_aggregate_kernel<<<agb, blk>>>(p_xl, p_xr, att1, bias1, p_h, Nn);

    // ---- layer 2 ----
    gemm2_kernel<0><<<dim3(gm, 1, 2), blk>>>(p_h, Wl2, bl2, p_xl, Wr2, br2, p_xr,
                                             Nn, 64, 64);
    gat_aggregate_kernel<<<agb, blk>>>(p_xl, p_xr, att2, bias2, p_h, Nn);

    // ---- output head: sigmoid(h @ Wo + bo) -> d_out ----
    gemm2_kernel<1><<<dim3(gm, 4, 1), blk>>>(p_h, Wo, bo, (float*)d_out,
                                             Wo, bo, (float*)d_out,
                                             Nn, 64, 256);
}

// round 5
// speedup vs baseline: 1.2017x; 1.2017x over previous
#include <cuda_runtime.h>

#define NMAX 50000
#define EMAX 1600000
#define HC   64
#define NEG_SLOPE 0.2f

// ---------------- device scratch (no allocation allowed) ----------------
__device__ float g_xl [NMAX * HC];     // source-side transform
__device__ float g_xr [NMAX * HC];     // target-side transform
__device__ float g_h  [NMAX * HC];     // activated layer output
__device__ int   g_deg[NMAX];          // in-degree histogram
__device__ int   g_off[NMAX + 1];      // CSR offsets
__device__ int   g_pos[NMAX];          // scatter cursors
__device__ int   g_csr_src[EMAX];      // src node per CSR slot (sorted by dst)
__device__ int   g_is64;               // 1 if edge_index is int64, 0 if int32

__device__ __forceinline__ float lrelu(float v) {
    return v > 0.f ? v : NEG_SLOPE * v;
}

// ---------------- edge_index dtype detection ------------------------------
__global__ void detect_dtype_kernel(const int* __restrict__ w) {
    if (threadIdx.x == 0 && blockIdx.x == 0) {
        int any = 0;
        for (int i = 0; i < 64; i++) any |= w[2 * i + 1];
        g_is64 = (any == 0) ? 1 : 0;
    }
}

__device__ __forceinline__ int load_idx(const void* ei, int i) {
    return g_is64 ? (int)((const long long*)ei)[i] : ((const int*)ei)[i];
}

// ---------------- CSR build (4 edges/thread for MLP) ----------------------
__global__ void hist_kernel(const void* __restrict__ ei, int E) {
    int base = (blockIdx.x * blockDim.x + threadIdx.x) * 4;
    if (base >= E) return;
    int n = E - base; if (n > 4) n = 4;
    int d[4];
#pragma unroll
    for (int j = 0; j < 4; j++)
        if (j < n) d[j] = load_idx(ei, base + j + E);
#pragma unroll
    for (int j = 0; j < 4; j++)
        if (j < n) atomicAdd(&g_deg[d[j]], 1);
}

__global__ void __launch_bounds__(1024) scan_kernel(int N) {
    __shared__ int part[1024];
    int t = threadIdx.x;
    int chunk = (N + 1023) >> 10;
    int b = t * chunk; if (b > N) b = N;
    int e = b + chunk; if (e > N) e = N;
    int s = 0;
    for (int i = b; i < e; i++) s += g_deg[i];
    part[t] = s;
    __syncthreads();
    for (int d = 1; d < 1024; d <<= 1) {
        int v = (t >= d) ? part[t - d] : 0;
        __syncthreads();
        part[t] += v;
        __syncthreads();
    }
    int run = (t == 0) ? 0 : part[t - 1];
    for (int i = b; i < e; i++) {
        g_off[i] = run;
        g_pos[i] = run;
        run += g_deg[i];
    }
    if (e == N) g_off[N] = run;
}

__global__ void scatter_kernel(const void* __restrict__ ei, int E) {
    int base = (blockIdx.x * blockDim.x + threadIdx.x) * 4;
    if (base >= E) return;
    int n = E - base; if (n > 4) n = 4;
    int s[4], d[4];
#pragma unroll
    for (int j = 0; j < 4; j++)
        if (j < n) { s[j] = load_idx(ei, base + j); d[j] = load_idx(ei, base + j + E); }
    int slot[4];
#pragma unroll
    for (int j = 0; j < 4; j++)
        if (j < n) slot[j] = atomicAdd(&g_pos[d[j]], 1);
#pragma unroll
    for (int j = 0; j < 4; j++)
        if (j < n) g_csr_src[slot[j]] = s[j];
}

// ---------------- dual GEMM (proven R3 tile; z selects weight set) --------
// C[z][M,NC] = A[M,K] @ W[z][K,NC] + bias[z].
// BM=128, BN=64, BK=32, 256 threads, 8x4 per-thread tile.
template<int ACT>  // 0 = none, 1 = sigmoid
__global__ void __launch_bounds__(256) gemm2_kernel(
    const float* __restrict__ A,
    const float* __restrict__ W0, const float* __restrict__ b0, float* __restrict__ C0,
    const float* __restrict__ W1, const float* __restrict__ b1, float* __restrict__ C1,
    int M, int K, int NC)
{
    const float* W    = blockIdx.z ? W1 : W0;
    const float* bias = blockIdx.z ? b1 : b0;
    float*       C    = blockIdx.z ? C1 : C0;

    __shared__ __align__(16) float As[32][132];   // [k][m], padded
    __shared__ __align__(16) float Ws[32][64];    // [k][n]

    const int tid = threadIdx.x;
    const int bm  = blockIdx.x * 128;
    const int bn  = blockIdx.y * 64;
    const int r0  = (tid >> 4) * 8;
    const int c0  = (tid & 15) * 4;

    float acc[8][4];
#pragma unroll
    for (int i = 0; i < 8; i++)
#pragma unroll
        for (int j = 0; j < 4; j++) acc[i][j] = 0.f;

    for (int kk = 0; kk < K; kk += 32) {
#pragma unroll
        for (int i = 0; i < 4; i++) {
            int f   = tid + i * 256;
            int row = f >> 3;
            int c4  = f & 7;
            float4 v = make_float4(0.f, 0.f, 0.f, 0.f);
            if (bm + row < M)
                v = *(const float4*)(A + (size_t)(bm + row) * K + kk + c4 * 4);
            As[c4 * 4 + 0][row] = v.x;
            As[c4 * 4 + 1][row] = v.y;
            As[c4 * 4 + 2][row] = v.z;
            As[c4 * 4 + 3][row] = v.w;
        }
#pragma unroll
        for (int i = 0; i < 2; i++) {
            int f  = tid + i * 256;
            int kr = f >> 4;
            int cw = (f & 15) * 4;
            *(float4*)&Ws[kr][cw] =
                *(const float4*)(W + (size_t)(kk + kr) * NC + bn + cw);
        }
        __syncthreads();

#pragma unroll
        for (int k = 0; k < 32; k++) {
            float4 a0 = *(const float4*)&As[k][r0];
            float4 a1 = *(const float4*)&As[k][r0 + 4];
            float4 w  = *(const float4*)&Ws[k][c0];
            float av[8] = {a0.x, a0.y, a0.z, a0.w, a1.x, a1.y, a1.z, a1.w};
            float wv[4] = {w.x, w.y, w.z, w.w};
#pragma unroll
            for (int i = 0; i < 8; i++)
#pragma unroll
                for (int j = 0; j < 4; j++)
                    acc[i][j] += av[i] * wv[j];
        }
        __syncthreads();
    }

    float4 bv = *(const float4*)(bias + bn + c0);
    float bvv[4] = {bv.x, bv.y, bv.z, bv.w};
#pragma unroll
    for (int i = 0; i < 8; i++) {
        int row = bm + r0 + i;
        if (row < M) {
            float o[4];
#pragma unroll
            for (int j = 0; j < 4; j++) {
                float v = acc[i][j] + bvv[j];
                if (ACT == 1) v = 1.f / (1.f + __expf(-v));
                o[j] = v;
            }
            *(float4*)(C + (size_t)row * NC + bn + c0) =
                make_float4(o[0], o[1], o[2], o[3]);
        }
    }
}

// ---------------- fused per-node GATv2 aggregation ------------------------
__device__ __forceinline__ void gat_edge_step(
    float2 xv, float2 xrv, float a0, float a1,
    float& accx, float& accy, float& den)
{
    float p = a0 * lrelu(xv.x + xrv.x) + a1 * lrelu(xv.y + xrv.y);
    p += __shfl_xor_sync(0xffffffffu, p, 1);
    p += __shfl_xor_sync(0xffffffffu, p, 2);
    p += __shfl_xor_sync(0xffffffffu, p, 4);
    float ex = __expf(p);
    den  += ex;
    accx += ex * xv.x;
    accy += ex * xv.y;
}

__global__ void __launch_bounds__(256) gat_aggregate_kernel(
    const float* __restrict__ xl, const float* __restrict__ xr,
    const float* __restrict__ att, const float* __restrict__ bias,
    float* __restrict__ out, int N)
{
    int warp = (blockIdx.x * blockDim.x + threadIdx.x) >> 5;
    int c    = threadIdx.x & 31;
    if (warp >= N) return;
    const int d = warp;

    const float a0 = att[2 * c];
    const float a1 = att[2 * c + 1];
    const float2 xrv = *(const float2*)(xr + (size_t)d * 64 + 2 * c);

    const int beg = g_off[d];
    const int end = g_off[d + 1];

    float accx = 0.f, accy = 0.f, den = 0.f;

    for (int i = beg; i < end; ) {
        int cnt = end - i;
        if (cnt > 32) cnt = 32;
        int my_src = (c < cnt) ? g_csr_src[i + c] : 0;

        int j = 0;
        for (; j + 4 <= cnt; j += 4) {
            int s0 = __shfl_sync(0xffffffffu, my_src, j);
            int s1 = __shfl_sync(0xffffffffu, my_src, j + 1);
            int s2 = __shfl_sync(0xffffffffu, my_src, j + 2);
            int s3 = __shfl_sync(0xffffffffu, my_src, j + 3);
            float2 v0 = *(const float2*)(xl + (size_t)s0 * 64 + 2 * c);
            float2 v1 = *(const float2*)(xl + (size_t)s1 * 64 + 2 * c);
            float2 v2 = *(const float2*)(xl + (size_t)s2 * 64 + 2 * c);
            float2 v3 = *(const float2*)(xl + (size_t)s3 * 64 + 2 * c);
            gat_edge_step(v0, xrv, a0, a1, accx, accy, den);
            gat_edge_step(v1, xrv, a0, a1, accx, accy, den);
            gat_edge_step(v2, xrv, a0, a1, accx, accy, den);
            gat_edge_step(v3, xrv, a0, a1, accx, accy, den);
        }
        for (; j < cnt; j++) {
            int s = __shfl_sync(0xffffffffu, my_src, j);
            float2 v = *(const float2*)(xl + (size_t)s * 64 + 2 * c);
            gat_edge_step(v, xrv, a0, a1, accx, accy, den);
        }
        i += cnt;
    }

    float inv = (den > 0.f) ? (1.f / den) : 0.f;
    float ox = fmaxf(accx * inv + bias[2 * c],     0.f);
    float oy = fmaxf(accy * inv + bias[2 * c + 1], 0.f);
    *(float2*)(out + (size_t)d * 64 + 2 * c) = make_float2(ox, oy);
}

// ---------------- launch --------------------------------------------------
extern "C" void kernel_launch(void* const* d_in, const int* in_sizes, int n_in,
                              void* d_out, int out_size)
{
    const float* x    = (const float*)d_in[0];
    const void*  ei   = d_in[1];
    const float* Wl1  = (const float*)d_in[2];
    const float* bl1  = (const float*)d_in[3];
    const float* Wr1  = (const float*)d_in[4];
    const float* br1  = (const float*)d_in[5];
    const float* att1 = (const float*)d_in[6];
    const float* bias1= (const float*)d_in[7];
    const float* Wl2  = (const float*)d_in[8];
    const float* bl2  = (const float*)d_in[9];
    const float* Wr2  = (const float*)d_in[10];
    const float* br2  = (const float*)d_in[11];
    const float* att2 = (const float*)d_in[12];
    const float* bias2= (const float*)d_in[13];
    const float* Wo   = (const float*)d_in[14];
    const float* bo   = (const float*)d_in[15];

    const int Nn = in_sizes[0] / 256;      // 50000
    const int E  = in_sizes[1] / 2;        // 1600000

    float *p_xl, *p_xr, *p_h;
    int *p_deg;
    cudaGetSymbolAddress((void**)&p_xl,  g_xl);
    cudaGetSymbolAddress((void**)&p_xr,  g_xr);
    cudaGetSymbolAddress((void**)&p_h,   g_h);
    cudaGetSymbolAddress((void**)&p_deg, g_deg);

    // side stream + events, created once OUTSIDE graph capture (first call
    // is the uncaptured correctness run). Deterministic work every call.
    static cudaStream_t s_csr = nullptr;
    static cudaEvent_t  ev_fork = nullptr, ev_join = nullptr;
    if (s_csr == nullptr) {
        cudaStreamCreateWithFlags(&s_csr, cudaStreamNonBlocking);
        cudaEventCreateWithFlags(&ev_fork, cudaEventDisableTiming);
        cudaEventCreateWithFlags(&ev_join, cudaEventDisableTiming);
    }

    const int gm = (Nn + 127) / 128;       // 391
    const dim3 blk(256);
    const int eb4 = (E / 4 + 255) / 256;   // 4 edges/thread
    const int agb = (Nn * 32 + 255) / 256;

    // ---- fork: CSR build on side stream, concurrent with layer-1 GEMM ----
    cudaEventRecord(ev_fork, 0);
    cudaStreamWaitEvent(s_csr, ev_fork, 0);

    detect_dtype_kernel<<<1, 32, 0, s_csr>>>((const int*)ei);
    cudaMemsetAsync(p_deg, 0, (size_t)Nn * sizeof(int), s_csr);
    hist_kernel<<<eb4, blk, 0, s_csr>>>(ei, E);
    scan_kernel<<<1, 1024, 0, s_csr>>>(Nn);
    scatter_kernel<<<eb4, blk, 0, s_csr>>>(ei, E);
    cudaEventRecord(ev_join, s_csr);

    // ---- layer 1 GEMMs (main stream, overlapped with CSR build) ----
    gemm2_kernel<0><<<dim3(gm, 1, 2), blk>>>(x, Wl1, bl1, p_xl, Wr1, br1, p_xr,
                                             Nn, 256, 64);

    // ---- join, then aggregate ----
    cudaStreamWaitEvent(0, ev_join, 0);
    gat_aggregate_kernel<<<agb, blk>>>(p_xl, p_xr, att1, bias1, p_h, Nn);

    // ---- layer 2 ----
    gemm2_kernel<0><<<dim3(gm, 1, 2), blk>>>(p_h, Wl2, bl2, p_xl, Wr2, br2, p_xr,
                                             Nn, 64, 64);
    gat_aggregate_kernel<<<agb, blk>>>(p_xl, p_xr, att2, bias2, p_h, Nn);

    // ---- output head: sigmoid(h @ Wo + bo) -> d_out ----
    gemm2_kernel<1><<<dim3(gm, 4, 1), blk>>>(p_h, Wo, bo, (float*)d_out,
                                             Wo, bo, (float*)d_out,
                                             Nn, 64, 256);
}

// round 7
// speedup vs baseline: 1.2231x; 1.0179x over previous
#include <cuda_runtime.h>
#include <cstdint>

#define NMAX 50000
#define EMAX 1600000
#define HC   64
#define NEG_SLOPE 0.2f

// ---------------- device scratch (no allocation allowed) ----------------
__device__ float g_xl [NMAX * HC];
__device__ float g_xr [NMAX * HC];
__device__ float g_h  [NMAX * HC];
__device__ int   g_deg[NMAX];
__device__ int   g_off[NMAX + 1];
__device__ int   g_pos[NMAX];
__device__ int   g_csr_src[EMAX];
__device__ int   g_is64;

__device__ __forceinline__ float lrelu(float v) {
    return v > 0.f ? v : NEG_SLOPE * v;
}

__device__ __forceinline__ uint32_t tf32_round(float x) {
    uint32_t r;
    asm("cvt.rna.tf32.f32 %0, %1;" : "=r"(r) : "f"(x));
    return r;
}

// ---------------- edge_index dtype detection ------------------------------
__global__ void detect_dtype_kernel(const int* __restrict__ w) {
    if (threadIdx.x == 0 && blockIdx.x == 0) {
        int any = 0;
        for (int i = 0; i < 64; i++) any |= w[2 * i + 1];
        g_is64 = (any == 0) ? 1 : 0;
    }
}
__device__ __forceinline__ int load_idx(const void* ei, int i) {
    return g_is64 ? (int)((const long long*)ei)[i] : ((const int*)ei)[i];
}

// ---------------- CSR build (4 edges/thread) ------------------------------
__global__ void hist_kernel(const void* __restrict__ ei, int E) {
    int base = (blockIdx.x * blockDim.x + threadIdx.x) * 4;
    if (base >= E) return;
    int n = E - base; if (n > 4) n = 4;
    int d[4];
#pragma unroll
    for (int j = 0; j < 4; j++)
        if (j < n) d[j] = load_idx(ei, base + j + E);
#pragma unroll
    for (int j = 0; j < 4; j++)
        if (j < n) atomicAdd(&g_deg[d[j]], 1);
}

__global__ void __launch_bounds__(1024) scan_kernel(int N) {
    __shared__ int part[1024];
    int t = threadIdx.x;
    int chunk = (N + 1023) >> 10;
    int b = t * chunk; if (b > N) b = N;
    int e = b + chunk; if (e > N) e = N;
    int s = 0;
    for (int i = b; i < e; i++) s += g_deg[i];
    part[t] = s;
    __syncthreads();
    for (int d = 1; d < 1024; d <<= 1) {
        int v = (t >= d) ? part[t - d] : 0;
        __syncthreads();
        part[t] += v;
        __syncthreads();
    }
    int run = (t == 0) ? 0 : part[t - 1];
    for (int i = b; i < e; i++) {
        g_off[i] = run;
        g_pos[i] = run;
        run += g_deg[i];
    }
    if (e == N) g_off[N] = run;
}

__global__ void scatter_kernel(const void* __restrict__ ei, int E) {
    int base = (blockIdx.x * blockDim.x + threadIdx.x) * 4;
    if (base >= E) return;
    int n = E - base; if (n > 4) n = 4;
    int s[4], d[4];
#pragma unroll
    for (int j = 0; j < 4; j++)
        if (j < n) { s[j] = load_idx(ei, base + j); d[j] = load_idx(ei, base + j + E); }
    int slot[4];
#pragma unroll
    for (int j = 0; j < 4; j++)
        if (j < n) slot[j] = atomicAdd(&g_pos[d[j]], 1);
#pragma unroll
    for (int j = 0; j < 4; j++)
        if (j < n) g_csr_src[slot[j]] = s[j];
}

// ---------------- split-tf32 mma.sync GEMM --------------------------------
// C[z][M,NC] = A[M,K] @ W[z][K,NC] + bias[z]; fp32-accurate via
// AhiBhi + AhiBlo + AloBhi. CTA tile 128x64, 8 warps (4M x 2N, 32x32 each),
// K-chunk 32, mma.sync.m16n8k8 tf32.
// Smem (floats): Ahi[128][36] | Alo[128][36] | Bhi[32][72] | Blo[32][72]
#define ASTRIDE 36
#define BSTRIDE 72
#define SM_FLOATS (2 * 128 * ASTRIDE + 2 * 32 * BSTRIDE)   // 13824
#define SM_BYTES  (SM_FLOATS * 4)                          // 55296

__device__ __forceinline__ void mma8(float* c, const uint32_t* a, const uint32_t* b) {
    asm volatile(
        "mma.sync.aligned.m16n8k8.row.col.f32.tf32.tf32.f32 "
        "{%0,%1,%2,%3}, {%4,%5,%6,%7}, {%8,%9}, {%0,%1,%2,%3};"
        : "+f"(c[0]), "+f"(c[1]), "+f"(c[2]), "+f"(c[3])
        : "r"(a[0]), "r"(a[1]), "r"(a[2]), "r"(a[3]), "r"(b[0]), "r"(b[1]));
}

template<int ACT>  // 0 = none, 1 = sigmoid
__global__ void __launch_bounds__(256) mma_gemm_kernel(
    const float* __restrict__ A,
    const float* __restrict__ W0, const float* __restrict__ b0, float* __restrict__ C0,
    const float* __restrict__ W1, const float* __restrict__ b1, float* __restrict__ C1,
    int M, int K, int NC)
{
    const float* W    = blockIdx.z ? W1 : W0;
    const float* bias = blockIdx.z ? b1 : b0;
    float*       C    = blockIdx.z ? C1 : C0;

    extern __shared__ float sm[];
    float* Ahi = sm;
    float* Alo = sm + 128 * ASTRIDE;
    float* Bhi = sm + 2 * 128 * ASTRIDE;
    float* Blo = Bhi + 32 * BSTRIDE;

    const int tid = threadIdx.x;
    const int wid = tid >> 5;
    const int lid = tid & 31;
    const int t   = lid & 3;      // threadID_in_group
    const int g   = lid >> 2;     // groupID
    const int wm  = wid & 3;      // warp M index (0..3)
    const int wn  = wid >> 2;     // warp N index (0..1)
    const int bm  = blockIdx.x * 128;
    const int bn  = blockIdx.y * 64;

    float acc[2][4][4];
#pragma unroll
    for (int i = 0; i < 2; i++)
#pragma unroll
        for (int j = 0; j < 4; j++)
#pragma unroll
            for (int q = 0; q < 4; q++) acc[i][j][q] = 0.f;

    for (int kk = 0; kk < K; kk += 32) {
        // ---- fill A chunk: 128 rows x 32 k, layout [m][k] stride 36 ----
#pragma unroll
        for (int it = 0; it < 4; it++) {
            int idx = tid + it * 256;          // 0..1023 float4 slots
            int row = idx >> 3;
            int c4  = (idx & 7) * 4;
            float4 v = make_float4(0.f, 0.f, 0.f, 0.f);
            if (bm + row < M)
                v = *(const float4*)(A + (size_t)(bm + row) * K + kk + c4);
            uint32_t h0 = tf32_round(v.x), h1 = tf32_round(v.y),
                     h2 = tf32_round(v.z), h3 = tf32_round(v.w);
            float4 hf = make_float4(__uint_as_float(h0), __uint_as_float(h1),
                                    __uint_as_float(h2), __uint_as_float(h3));
            float4 lf = make_float4(
                __uint_as_float(tf32_round(v.x - hf.x)),
                __uint_as_float(tf32_round(v.y - hf.y)),
                __uint_as_float(tf32_round(v.z - hf.z)),
                __uint_as_float(tf32_round(v.w - hf.w)));
            *(float4*)(Ahi + row * ASTRIDE + c4) = hf;
            *(float4*)(Alo + row * ASTRIDE + c4) = lf;
        }
        // ---- fill B chunk: Bs[k][n] = W[kk+k][bn+n], 32 x 64, stride 72 ----
#pragma unroll
        for (int it = 0; it < 2; it++) {
            int idx = tid + it * 256;          // 0..511 float4 slots
            int kr  = idx >> 4;
            int cw  = (idx & 15) * 4;
            float4 v = *(const float4*)(W + (size_t)(kk + kr) * NC + bn + cw);
            float4 hf = make_float4(
                __uint_as_float(tf32_round(v.x)), __uint_as_float(tf32_round(v.y)),
                __uint_as_float(tf32_round(v.z)), __uint_as_float(tf32_round(v.w)));
            float4 lf = make_float4(
                __uint_as_float(tf32_round(v.x - hf.x)),
                __uint_as_float(tf32_round(v.y - hf.y)),
                __uint_as_float(tf32_round(v.z - hf.z)),
                __uint_as_float(tf32_round(v.w - hf.w)));
            *(float4*)(Bhi + kr * BSTRIDE + cw) = hf;
            *(float4*)(Blo + kr * BSTRIDE + cw) = lf;
        }
        __syncthreads();

        // ---- 4 k-steps of m16n8k8 ----
#pragma unroll
        for (int q = 0; q < 4; q++) {
            const int kq = q * 8;
            uint32_t ahi[2][4], alo[2][4];
#pragma unroll
            for (int i = 0; i < 2; i++) {
                int mb = wm * 32 + i * 16;
                const uint32_t* ph = (const uint32_t*)Ahi;
                const uint32_t* pl = (const uint32_t*)Alo;
                int o00 = (mb + g)     * ASTRIDE + kq + t;
                int o10 = (mb + g + 8) * ASTRIDE + kq + t;
                ahi[i][0] = ph[o00];     ahi[i][1] = ph[o10];
                ahi[i][2] = ph[o00 + 4]; ahi[i][3] = ph[o10 + 4];
                alo[i][0] = pl[o00];     alo[i][1] = pl[o10];
                alo[i][2] = pl[o00 + 4]; alo[i][3] = pl[o10 + 4];
            }
            uint32_t bhi[4][2], blo[4][2];
#pragma unroll
            for (int j = 0; j < 4; j++) {
                int nb = wn * 32 + j * 8;
                const uint32_t* ph = (const uint32_t*)Bhi;
                const uint32_t* pl = (const uint32_t*)Blo;
                int o0 = (kq + t)     * BSTRIDE + nb + g;
                int o1 = (kq + t + 4) * BSTRIDE + nb + g;
                bhi[j][0] = ph[o0]; bhi[j][1] = ph[o1];
                blo[j][0] = pl[o0]; blo[j][1] = pl[o1];
            }
#pragma unroll
            for (int i = 0; i < 2; i++)
#pragma unroll
                for (int j = 0; j < 4; j++) {
                    mma8(acc[i][j], ahi[i], bhi[j]);
                    mma8(acc[i][j], ahi[i], blo[j]);
                    mma8(acc[i][j], alo[i], bhi[j]);
                }
        }
        __syncthreads();
    }

    // ---- epilogue ----
#pragma unroll
    for (int i = 0; i < 2; i++) {
        int r0 = bm + wm * 32 + i * 16 + g;
#pragma unroll
        for (int j = 0; j < 4; j++) {
            int col = bn + wn * 32 + j * 8 + 2 * t;
            float bz0 = bias[col], bz1 = bias[col + 1];
            float v0 = acc[i][j][0] + bz0;
            float v1 = acc[i][j][1] + bz1;
            float v2 = acc[i][j][2] + bz0;
            float v3 = acc[i][j][3] + bz1;
            if (ACT == 1) {
                v0 = 1.f / (1.f + __expf(-v0));
                v1 = 1.f / (1.f + __expf(-v1));
                v2 = 1.f / (1.f + __expf(-v2));
                v3 = 1.f / (1.f + __expf(-v3));
            }
            if (r0 < M)
                *(float2*)(C + (size_t)r0 * NC + col) = make_float2(v0, v1);
            if (r0 + 8 < M)
                *(float2*)(C + (size_t)(r0 + 8) * NC + col) = make_float2(v2, v3);
        }
    }
}

// ---------------- fused per-node GATv2 aggregation ------------------------
__device__ __forceinline__ void gat_edge_step(
    float2 xv, float2 xrv, float a0, float a1,
    float& accx, float& accy, float& den)
{
    float p = a0 * lrelu(xv.x + xrv.x) + a1 * lrelu(xv.y + xrv.y);
    p += __shfl_xor_sync(0xffffffffu, p, 1);
    p += __shfl_xor_sync(0xffffffffu, p, 2);
    p += __shfl_xor_sync(0xffffffffu, p, 4);
    float ex = __expf(p);
    den  += ex;
    accx += ex * xv.x;
    accy += ex * xv.y;
}

__global__ void __launch_bounds__(256) gat_aggregate_kernel(
    const float* __restrict__ xl, const float* __restrict__ xr,
    const float* __restrict__ att, const float* __restrict__ bias,
    float* __restrict__ out, int N)
{
    int warp = (blockIdx.x * blockDim.x + threadIdx.x) >> 5;
    int c    = threadIdx.x & 31;
    if (warp >= N) return;
    const int d = warp;

    const float a0 = att[2 * c];
    const float a1 = att[2 * c + 1];
    const float2 xrv = *(const float2*)(xr + (size_t)d * 64 + 2 * c);

    const int beg = g_off[d];
    const int end = g_off[d + 1];

    float accx = 0.f, accy = 0.f, den = 0.f;

    for (int i = beg; i < end; ) {
        int cnt = end - i;
        if (cnt > 32) cnt = 32;
        int my_src = (c < cnt) ? g_csr_src[i + c] : 0;

        int j = 0;
        for (; j + 4 <= cnt; j += 4) {
            int s0 = __shfl_sync(0xffffffffu, my_src, j);
            int s1 = __shfl_sync(0xffffffffu, my_src, j + 1);
            int s2 = __shfl_sync(0xffffffffu, my_src, j + 2);
            int s3 = __shfl_sync(0xffffffffu, my_src, j + 3);
            float2 v0 = *(const float2*)(xl + (size_t)s0 * 64 + 2 * c);
            float2 v1 = *(const float2*)(xl + (size_t)s1 * 64 + 2 * c);
            float2 v2 = *(const float2*)(xl + (size_t)s2 * 64 + 2 * c);
            float2 v3 = *(const float2*)(xl + (size_t)s3 * 64 + 2 * c);
            gat_edge_step(v0, xrv, a0, a1, accx, accy, den);
            gat_edge_step(v1, xrv, a0, a1, accx, accy, den);
            gat_edge_step(v2, xrv, a0, a1, accx, accy, den);
            gat_edge_step(v3, xrv, a0, a1, accx, accy, den);
        }
        for (; j < cnt; j++) {
            int s = __shfl_sync(0xffffffffu, my_src, j);
            float2 v = *(const float2*)(xl + (size_t)s * 64 + 2 * c);
            gat_edge_step(v, xrv, a0, a1, accx, accy, den);
        }
        i += cnt;
    }

    float inv = (den > 0.f) ? (1.f / den) : 0.f;
    float ox = fmaxf(accx * inv + bias[2 * c],     0.f);
    float oy = fmaxf(accy * inv + bias[2 * c + 1], 0.f);
    *(float2*)(out + (size_t)d * 64 + 2 * c) = make_float2(ox, oy);
}

// ---------------- launch --------------------------------------------------
extern "C" void kernel_launch(void* const* d_in, const int* in_sizes, int n_in,
                              void* d_out, int out_size)
{
    const float* x    = (const float*)d_in[0];
    const void*  ei   = d_in[1];
    const float* Wl1  = (const float*)d_in[2];
    const float* bl1  = (const float*)d_in[3];
    const float* Wr1  = (const float*)d_in[4];
    const float* br1  = (const float*)d_in[5];
    const float* att1 = (const float*)d_in[6];
    const float* bias1= (const float*)d_in[7];
    const float* Wl2  = (const float*)d_in[8];
    const float* bl2  = (const float*)d_in[9];
    const float* Wr2  = (const float*)d_in[10];
    const float* br2  = (const float*)d_in[11];
    const float* att2 = (const float*)d_in[12];
    const float* bias2= (const float*)d_in[13];
    const float* Wo   = (const float*)d_in[14];
    const float* bo   = (const float*)d_in[15];

    const int Nn = in_sizes[0] / 256;      // 50000
    const int E  = in_sizes[1] / 2;        // 1600000

    float *p_xl, *p_xr, *p_h;
    int *p_deg;
    cudaGetSymbolAddress((void**)&p_xl,  g_xl);
    cudaGetSymbolAddress((void**)&p_xr,  g_xr);
    cudaGetSymbolAddress((void**)&p_h,   g_h);
    cudaGetSymbolAddress((void**)&p_deg, g_deg);

    static cudaStream_t s_csr = nullptr;
    static cudaEvent_t  ev_fork = nullptr, ev_join = nullptr;
    if (s_csr == nullptr) {
        cudaStreamCreateWithFlags(&s_csr, cudaStreamNonBlocking);
        cudaEventCreateWithFlags(&ev_fork, cudaEventDisableTiming);
        cudaEventCreateWithFlags(&ev_join, cudaEventDisableTiming);
        cudaFuncSetAttribute(mma_gemm_kernel<0>,
                             cudaFuncAttributeMaxDynamicSharedMemorySize, SM_BYTES);
        cudaFuncSetAttribute(mma_gemm_kernel<1>,
                             cudaFuncAttributeMaxDynamicSharedMemorySize, SM_BYTES);
    }

    const int gm = (Nn + 127) / 128;       // 391
    const int eb4 = (E / 4 + 255) / 256;
    const int agb = (Nn * 32 + 255) / 256;

    // ---- fork: CSR build on side stream, concurrent with layer-1 GEMM ----
    cudaEventRecord(ev_fork, 0);
    cudaStreamWaitEvent(s_csr, ev_fork, 0);

    detect_dtype_kernel<<<1, 32, 0, s_csr>>>((const int*)ei);
    cudaMemsetAsync(p_deg, 0, (size_t)Nn * sizeof(int), s_csr);
    hist_kernel<<<eb4, 256, 0, s_csr>>>(ei, E);
    scan_kernel<<<1, 1024, 0, s_csr>>>(Nn);
    scatter_kernel<<<eb4, 256, 0, s_csr>>>(ei, E);
    cudaEventRecord(ev_join, s_csr);

    // ---- layer 1 GEMMs (tensor via mma.sync) ----
    mma_gemm_kernel<0><<<dim3(gm, 1, 2), 256, SM_BYTES>>>(
        x, Wl1, bl1, p_xl, Wr1, br1, p_xr, Nn, 256, 64);

    cudaStreamWaitEvent(0, ev_join, 0);
    gat_aggregate_kernel<<<agb, 256>>>(p_xl, p_xr, att1, bias1, p_h, Nn);

    // ---- layer 2 ----
    mma_gemm_kernel<0><<<dim3(gm, 1, 2), 256, SM_BYTES>>>(
        p_h, Wl2, bl2, p_xl, Wr2, br2, p_xr, Nn, 64, 64);
    gat_aggregate_kernel<<<agb, 256>>>(p_xl, p_xr, att2, bias2, p_h, Nn);

    // ---- output head: sigmoid(h @ Wo + bo) -> d_out ----
    mma_gemm_kernel<1><<<dim3(gm, 4, 1), 256, SM_BYTES>>>(
        p_h, Wo, bo, (float*)d_out, Wo, bo, (float*)d_out, Nn, 64, 256);
}